// round 1
// baseline (speedup 1.0000x reference)
#include <cuda_runtime.h>
#include <cstdint>

typedef unsigned long long ull;

// ---------------- device scratch (static, no runtime alloc) ----------------
__device__ float g_s1[2048 * 32 * 14 * 14];   // stage1 out: [B,32,14,14]
__device__ float g_s2[2048 * 3136];           // stage2 out: [B,64*7*7]
__device__ float g_fc1[2048 * 1024];          // fc1 out
__device__ float g_w2t[32 * 25 * 64];         // conv2 w transposed: [ci][tap][co]

// ---------------- f32x2 helpers (FFMA2 full-rate fp32 path) ----------------
__device__ __forceinline__ ull ffma2(ull a, ull b, ull c) {
    ull d;
    asm("fma.rn.f32x2 %0, %1, %2, %3;" : "=l"(d) : "l"(a), "l"(b), "l"(c));
    return d;
}
__device__ __forceinline__ ull dup2(float v) {
    ull d; asm("mov.b64 %0, {%1, %1};" : "=l"(d) : "f"(v)); return d;
}
__device__ __forceinline__ ull pk2(float lo, float hi) {
    ull d; asm("mov.b64 %0, {%1, %2};" : "=l"(d) : "f"(lo), "f"(hi)); return d;
}
__device__ __forceinline__ void upk2(ull v, float& lo, float& hi) {
    asm("mov.b64 {%0, %1}, %2;" : "=f"(lo), "=f"(hi) : "l"(v));
}

// ---------------- cp.async helpers ----------------
__device__ __forceinline__ void cp16(float* s, const float* g) {
    unsigned sa = (unsigned)__cvta_generic_to_shared(s);
    asm volatile("cp.async.ca.shared.global [%0], [%1], 16;" :: "r"(sa), "l"(g));
}
__device__ __forceinline__ void cp_commit() { asm volatile("cp.async.commit_group;"); }
__device__ __forceinline__ void cp_wait0()  { asm volatile("cp.async.wait_group 0;"); }

// ---------------- top-4 insertion (a>=b>=c>=d) ----------------
__device__ __forceinline__ void ins4(float& a, float& b, float& c, float& d, float v) {
    if (v > d) {
        d = v;
        if (d > c) { float t = c; c = d; d = t;
            if (c > b) { t = b; b = c; c = t;
                if (b > a) { t = a; a = b; b = t; }
            }
        }
    }
}

// ============================================================================
// prep: transpose conv2_w [co][ci][tap] -> [ci][tap][co]
// ============================================================================
__global__ void k_prep(const float* __restrict__ w2) {
    int i = blockIdx.x * blockDim.x + threadIdx.x;
    if (i < 64 * 32 * 25) {
        int co = i / 800, r = i % 800, ci = r / 25, tap = r % 25;
        g_w2t[(ci * 25 + tap) * 64 + co] = w2[i];
    }
}

// ============================================================================
// conv1 (1->32, 5x5, pad2) + top-4 channel mask + threshold ReLU + 2x2 maxpool
// block = 2 images, 392 threads; thread = one 2x2 output quad.
// f32x2 lanes = (top pixel, bottom pixel); two accumulators = two columns.
// ============================================================================
__global__ void __launch_bounds__(392) k_conv1(const float* __restrict__ xin,
                                               const float* __restrict__ w1,
                                               const float* __restrict__ tt) {
    __shared__ float s_in[2][1024];     // padded 32x32 per image
    __shared__ ull   s_w[800];          // dup-packed weights (w,w)
    __shared__ float s_t[32];

    int tid = threadIdx.x;
    int img0 = blockIdx.x * 2;

    for (int i = tid; i < 800; i += 392) { float v = w1[i]; s_w[i] = dup2(v); }
    if (tid < 32) s_t[tid] = tt[tid];
    for (int i = tid; i < 2048; i += 392) ((float*)s_in)[i] = 0.f;
    __syncthreads();
    for (int i = tid; i < 1568; i += 392) {
        int im = i / 784, p = i % 784, y = p / 28, xx = p % 28;
        s_in[im][(y + 2) * 32 + xx + 2] = xin[(img0 + im) * 784 + p];
    }
    __syncthreads();

    int im = tid / 196, t = tid % 196;
    int py = t / 14, px = t % 14;
    const float* base = &s_in[im][(2 * py) * 32 + 2 * px];

    // window 6x6, packed vertical pairs pr[dy][c] = (row dy, row dy+1), dy 0..4, c 0..5
    float win[6][6];
#pragma unroll
    for (int r = 0; r < 6; r++)
#pragma unroll
        for (int c = 0; c < 6; c++) win[r][c] = base[r * 32 + c];
    ull pr[30];
#pragma unroll
    for (int dy = 0; dy < 5; dy++)
#pragma unroll
        for (int c = 0; c < 6; c++) pr[dy * 6 + c] = pk2(win[dy][c], win[dy + 1][c]);

    // pass A: top-4 per pixel
    float a0t = -3.4e38f, b0t = -3.4e38f, c0t = -3.4e38f, d0t = -3.4e38f;
    float a1t = -3.4e38f, b1t = -3.4e38f, c1t = -3.4e38f, d1t = -3.4e38f;
    float a2t = -3.4e38f, b2t = -3.4e38f, c2t = -3.4e38f, d2t = -3.4e38f;
    float a3t = -3.4e38f, b3t = -3.4e38f, c3t = -3.4e38f, d3t = -3.4e38f;

    for (int c = 0; c < 32; c++) {
        const ull* wc = &s_w[c * 25];
        ull A0 = 0ull, A1 = 0ull;
#pragma unroll
        for (int dy = 0; dy < 5; dy++)
#pragma unroll
            for (int dx = 0; dx < 5; dx++) {
                ull wv = wc[dy * 5 + dx];
                A0 = ffma2(pr[dy * 6 + dx], wv, A0);
                A1 = ffma2(pr[dy * 6 + dx + 1], wv, A1);
            }
        float v00, v10, v01, v11;
        upk2(A0, v00, v10); upk2(A1, v01, v11);
        ins4(a0t, b0t, c0t, d0t, v00);
        ins4(a1t, b1t, c1t, d1t, v10);
        ins4(a2t, b2t, c2t, d2t, v01);
        ins4(a3t, b3t, c3t, d3t, v11);
    }
    float k0 = d0t, k1 = d1t, k2 = d2t, k3 = d3t;

    // pass B: recompute, mask by kth, threshold-relu, 2x2 max, store
    int img = img0 + im;
    for (int c = 0; c < 32; c++) {
        const ull* wc = &s_w[c * 25];
        ull A0 = 0ull, A1 = 0ull;
#pragma unroll
        for (int dy = 0; dy < 5; dy++)
#pragma unroll
            for (int dx = 0; dx < 5; dx++) {
                ull wv = wc[dy * 5 + dx];
                A0 = ffma2(pr[dy * 6 + dx], wv, A0);
                A1 = ffma2(pr[dy * 6 + dx + 1], wv, A1);
            }
        float v00, v10, v01, v11;
        upk2(A0, v00, v10); upk2(A1, v01, v11);
        float tc = s_t[c];
        float r0 = (v00 >= k0) ? fmaxf(v00 - tc, 0.f) : 0.f;
        float r1 = (v10 >= k1) ? fmaxf(v10 - tc, 0.f) : 0.f;
        float r2 = (v01 >= k2) ? fmaxf(v01 - tc, 0.f) : 0.f;
        float r3 = (v11 >= k3) ? fmaxf(v11 - tc, 0.f) : 0.f;
        float m = fmaxf(fmaxf(r0, r1), fmaxf(r2, r3));
        g_s1[((img * 32 + c) * 14 + py) * 14 + px] = m;
    }
}

// ============================================================================
// conv2 (32->64, 5x5, pad2, 14x14) + bias + relu + 2x2 maxpool
// block = 2 images, 392 threads: thread = (image, co-half of 32, vertical
// pixel pair). f32x2 lanes = adjacent output channels. Weights staged per-ci
// via cp.async double buffer; broadcast LDS.128 reads.
// ============================================================================
__global__ void __launch_bounds__(392) k_conv2(const float* __restrict__ b2) {
    extern __shared__ float sm[];
    float* s_in = sm;              // 2 * 32*18*18 = 20736 floats (padded inputs)
    float* s_w  = sm + 20736;      // 2 * 1600 floats (double-buffered w slice)

    int tid = threadIdx.x;
    int img0 = blockIdx.x * 2;

    for (int i = tid; i < 20736; i += 392) s_in[i] = 0.f;
    __syncthreads();
    for (int i = tid; i < 12544; i += 392) {
        int im = i / 6272, r = i % 6272, ci = r / 196, p = r % 196;
        int y = p / 14, xx = p % 14;
        s_in[im * 10368 + ci * 324 + (y + 2) * 18 + xx + 2] =
            g_s1[(((img0 + im) * 32 + ci) * 14 + y) * 14 + xx];
    }
    // prefetch weights for ci=0
    for (int i = tid; i < 400; i += 392) cp16(&s_w[i * 4], g_w2t + i * 4);
    cp_commit();

    int im = tid / 196, t = tid % 196, h = t / 98, q = t % 98;
    int qy = q / 14, xx = q % 14;
    const float* inb = s_in + im * 10368;
    int rowbase = (2 * qy) * 18 + xx;
    int coB = h * 32;

    ull acc0[16], acc1[16];
#pragma unroll
    for (int j = 0; j < 16; j++) { acc0[j] = 0ull; acc1[j] = 0ull; }

    for (int ci = 0; ci < 32; ci++) {
        cp_wait0();
        __syncthreads();
        int buf = ci & 1;
        if (ci < 31) {
            const float* src = g_w2t + (ci + 1) * 1600;
            float* dst = s_w + (1 - buf) * 1600;
            for (int i = tid; i < 400; i += 392) cp16(dst + i * 4, src + i * 4);
            cp_commit();
        }
        const float* ip = inb + ci * 324 + rowbase;
        const float* wp = s_w + buf * 1600 + coB;

        ull rA[5], rB[5];
#pragma unroll
        for (int c = 0; c < 5; c++) rA[c] = dup2(ip[c]);
#pragma unroll
        for (int dy = 0; dy < 5; dy++) {
            const float* rp = ip + (dy + 1) * 18;
#pragma unroll
            for (int c = 0; c < 5; c++) rB[c] = dup2(rp[c]);
#pragma unroll
            for (int dx = 0; dx < 5; dx++) {
                const ulonglong2* wv =
                    reinterpret_cast<const ulonglong2*>(wp + (dy * 5 + dx) * 64);
                ull ra = rA[dx], rb = rB[dx];
#pragma unroll
                for (int jj = 0; jj < 8; jj++) {
                    ulonglong2 ww = wv[jj];
                    acc0[2 * jj]     = ffma2(ra, ww.x, acc0[2 * jj]);
                    acc0[2 * jj + 1] = ffma2(ra, ww.y, acc0[2 * jj + 1]);
                    acc1[2 * jj]     = ffma2(rb, ww.x, acc1[2 * jj]);
                    acc1[2 * jj + 1] = ffma2(rb, ww.y, acc1[2 * jj + 1]);
                }
            }
#pragma unroll
            for (int c = 0; c < 5; c++) rA[c] = rB[c];
        }
    }

    // epilogue: bias + relu + vertical max -> smem -> horizontal max -> store
    __syncthreads();
    float* sx = sm;  // reuse input region (padded stride 33 vs bank conflicts)
#pragma unroll
    for (int jj = 0; jj < 16; jj++) {
        float a, b, c, d;
        upk2(acc0[jj], a, b);
        upk2(acc1[jj], c, d);
        int co = coB + 2 * jj;
        float b0 = b2[co], b1 = b2[co + 1];
        float m0 = fmaxf(fmaxf(a + b0, 0.f), fmaxf(c + b0, 0.f));
        float m1 = fmaxf(fmaxf(b + b1, 0.f), fmaxf(d + b1, 0.f));
        sx[tid * 33 + 2 * jj] = m0;
        sx[tid * 33 + 2 * jj + 1] = m1;
    }
    __syncthreads();
    if (!(xx & 1)) {
        int img = img0 + im;
        int qx = xx >> 1;
#pragma unroll
        for (int c = 0; c < 32; c++) {
            float v = fmaxf(sx[tid * 33 + c], sx[(tid + 1) * 33 + c]);
            g_s2[img * 3136 + (coB + c) * 49 + qy * 7 + qx] = v;
        }
    }
}

// ============================================================================
// fc1: [2048,3136] x [1024,3136]^T + b, relu. Tiled GEMM BM=128 BN=64 BK=16,
// 256 threads, 8x4 microtile, f32x2 accumulation, double-buffered smem.
// ============================================================================
__global__ void __launch_bounds__(256) k_fc1(const float* __restrict__ w,
                                             const float* __restrict__ b) {
    __shared__ __align__(16) float As[2][16][132];
    __shared__ __align__(16) float Bs[2][16][68];

    int tid = threadIdx.x;
    int bm0 = blockIdx.x * 128, bn0 = blockIdx.y * 64;
    int tm = tid >> 4, tn = tid & 15;
    int m0 = tm * 8, n0 = tn * 4;
    int arow = tid >> 2, akq = tid & 3;

    ull acc[8][2];
#pragma unroll
    for (int i = 0; i < 8; i++) { acc[i][0] = 0ull; acc[i][1] = 0ull; }

    float4 aR0, aR1, bR;
    {
        int k0 = 0;
        aR0 = *reinterpret_cast<const float4*>(&g_s2[(bm0 + arow) * 3136 + k0 + akq * 4]);
        aR1 = *reinterpret_cast<const float4*>(&g_s2[(bm0 + arow + 64) * 3136 + k0 + akq * 4]);
        bR  = *reinterpret_cast<const float4*>(&w[(bn0 + arow) * 3136 + k0 + akq * 4]);
    }
    {
        int kb = akq * 4;
        As[0][kb + 0][arow] = aR0.x; As[0][kb + 1][arow] = aR0.y;
        As[0][kb + 2][arow] = aR0.z; As[0][kb + 3][arow] = aR0.w;
        As[0][kb + 0][arow + 64] = aR1.x; As[0][kb + 1][arow + 64] = aR1.y;
        As[0][kb + 2][arow + 64] = aR1.z; As[0][kb + 3][arow + 64] = aR1.w;
        Bs[0][kb + 0][arow] = bR.x; Bs[0][kb + 1][arow] = bR.y;
        Bs[0][kb + 2][arow] = bR.z; Bs[0][kb + 3][arow] = bR.w;
    }
    __syncthreads();

    for (int kt = 0; kt < 196; kt++) {
        int s = kt & 1;
        if (kt < 195) {
            int k0 = (kt + 1) * 16;
            aR0 = *reinterpret_cast<const float4*>(&g_s2[(bm0 + arow) * 3136 + k0 + akq * 4]);
            aR1 = *reinterpret_cast<const float4*>(&g_s2[(bm0 + arow + 64) * 3136 + k0 + akq * 4]);
            bR  = *reinterpret_cast<const float4*>(&w[(bn0 + arow) * 3136 + k0 + akq * 4]);
        }
#pragma unroll
        for (int k = 0; k < 16; k++) {
            float4 a0 = *reinterpret_cast<const float4*>(&As[s][k][m0]);
            float4 a1 = *reinterpret_cast<const float4*>(&As[s][k][m0 + 4]);
            float4 b4 = *reinterpret_cast<const float4*>(&Bs[s][k][n0]);
            ull pb0 = pk2(b4.x, b4.y), pb1 = pk2(b4.z, b4.w);
            ull pa;
            pa = dup2(a0.x); acc[0][0] = ffma2(pa, pb0, acc[0][0]); acc[0][1] = ffma2(pa, pb1, acc[0][1]);
            pa = dup2(a0.y); acc[1][0] = ffma2(pa, pb0, acc[1][0]); acc[1][1] = ffma2(pa, pb1, acc[1][1]);
            pa = dup2(a0.z); acc[2][0] = ffma2(pa, pb0, acc[2][0]); acc[2][1] = ffma2(pa, pb1, acc[2][1]);
            pa = dup2(a0.w); acc[3][0] = ffma2(pa, pb0, acc[3][0]); acc[3][1] = ffma2(pa, pb1, acc[3][1]);
            pa = dup2(a1.x); acc[4][0] = ffma2(pa, pb0, acc[4][0]); acc[4][1] = ffma2(pa, pb1, acc[4][1]);
            pa = dup2(a1.y); acc[5][0] = ffma2(pa, pb0, acc[5][0]); acc[5][1] = ffma2(pa, pb1, acc[5][1]);
            pa = dup2(a1.z); acc[6][0] = ffma2(pa, pb0, acc[6][0]); acc[6][1] = ffma2(pa, pb1, acc[6][1]);
            pa = dup2(a1.w); acc[7][0] = ffma2(pa, pb0, acc[7][0]); acc[7][1] = ffma2(pa, pb1, acc[7][1]);
        }
        if (kt < 195) {
            int ns = 1 - s;
            int kb = akq * 4;
            As[ns][kb + 0][arow] = aR0.x; As[ns][kb + 1][arow] = aR0.y;
            As[ns][kb + 2][arow] = aR0.z; As[ns][kb + 3][arow] = aR0.w;
            As[ns][kb + 0][arow + 64] = aR1.x; As[ns][kb + 1][arow + 64] = aR1.y;
            As[ns][kb + 2][arow + 64] = aR1.z; As[ns][kb + 3][arow + 64] = aR1.w;
            Bs[ns][kb + 0][arow] = bR.x; Bs[ns][kb + 1][arow] = bR.y;
            Bs[ns][kb + 2][arow] = bR.z; Bs[ns][kb + 3][arow] = bR.w;
            __syncthreads();
        }
    }

#pragma unroll
    for (int i = 0; i < 8; i++) {
        int m = bm0 + m0 + i, gn = bn0 + n0;
        float r0, r1, r2, r3;
        upk2(acc[i][0], r0, r1);
        upk2(acc[i][1], r2, r3);
        float4 o;
        o.x = fmaxf(r0 + b[gn + 0], 0.f);
        o.y = fmaxf(r1 + b[gn + 1], 0.f);
        o.z = fmaxf(r2 + b[gn + 2], 0.f);
        o.w = fmaxf(r3 + b[gn + 3], 0.f);
        *reinterpret_cast<float4*>(&g_fc1[m * 1024 + gn]) = o;
    }
}

// ============================================================================
// fc2: [2048,1024] x [10,1024]^T + b. Warp per row.
// ============================================================================
__global__ void __launch_bounds__(256) k_fc2(const float* __restrict__ w,
                                             const float* __restrict__ b,
                                             float* __restrict__ out) {
    int warp = threadIdx.x >> 5, lane = threadIdx.x & 31;
    int row = blockIdx.x * 8 + warp;
    const float* a = &g_fc1[row * 1024];
    float acc[10];
#pragma unroll
    for (int n = 0; n < 10; n++) acc[n] = 0.f;
    for (int k = lane; k < 1024; k += 32) {
        float av = a[k];
#pragma unroll
        for (int n = 0; n < 10; n++) acc[n] += av * w[n * 1024 + k];
    }
#pragma unroll
    for (int n = 0; n < 10; n++)
#pragma unroll
        for (int off = 16; off > 0; off >>= 1)
            acc[n] += __shfl_xor_sync(0xffffffffu, acc[n], off);
    if (lane == 0) {
#pragma unroll
        for (int n = 0; n < 10; n++) out[row * 10 + n] = acc[n] + b[n];
    }
}

// ============================================================================
extern "C" void kernel_launch(void* const* d_in, const int* in_sizes, int n_in,
                              void* d_out, int out_size) {
    const float* x       = (const float*)d_in[0];
    const float* conv1_w = (const float*)d_in[1];
    const float* trelu_t = (const float*)d_in[2];
    const float* conv2_w = (const float*)d_in[3];
    const float* conv2_b = (const float*)d_in[4];
    const float* fc1_w   = (const float*)d_in[5];
    const float* fc1_b   = (const float*)d_in[6];
    const float* fc2_w   = (const float*)d_in[7];
    const float* fc2_b   = (const float*)d_in[8];
    float* out = (float*)d_out;

    const int SMEM2 = (2 * 10368 + 2 * 1600) * 4;  // 95744 B
    cudaFuncSetAttribute(k_conv2, cudaFuncAttributeMaxDynamicSharedMemorySize, SMEM2);

    k_prep<<<(64 * 32 * 25 + 255) / 256, 256>>>(conv2_w);
    k_conv1<<<1024, 392>>>(x, conv1_w, trelu_t);
    k_conv2<<<1024, 392, SMEM2>>>(conv2_b);
    k_fc1<<<dim3(16, 16), 256>>>(fc1_w, fc1_b);
    k_fc2<<<256, 256>>>(fc2_w, fc2_b, out);
}